// round 3
// baseline (speedup 1.0000x reference)
#include <cuda_runtime.h>

#define NN 20000
#define NE 80000
#define D  128
#define ITERS 15
#define EPSLN 1e-5f
#define PA 129   // A-tile shared-memory pitch (odd -> conflict-free row-group loads)

// Scratch state (allocation-free rule: __device__ globals)
__device__ float g_x[NN * D];     // node features
__device__ float g_e[NE * D];     // edge features
__device__ float g_agg[NN * D];   // scatter-sum accumulator

#define SMEM_BYTES ((128 * PA + 128 * 128) * 4 + 256 * 4)

// ---------------- packed f32x2 helpers ----------------
__device__ __forceinline__ unsigned long long pack2(float lo, float hi) {
    unsigned long long r;
    asm("mov.b64 %0, {%1, %2};" : "=l"(r) : "f"(lo), "f"(hi));
    return r;
}
__device__ __forceinline__ void unpack2(unsigned long long v, float& lo, float& hi) {
    asm("mov.b64 {%0, %1}, %2;" : "=f"(lo), "=f"(hi) : "l"(v));
}
__device__ __forceinline__ void ffma2(unsigned long long& d, unsigned long long a, unsigned long long b) {
    asm("fma.rn.f32x2 %0, %1, %2, %0;" : "+l"(d) : "l"(a), "l"(b));
}

// ---------------- 128x128x128 fp32 GEMM tile (accumulate) ----------------
// Thread layout: 256 threads = 16(tx) x 16(ty).
// Micro-tile: rows r = ty + 16*i (i=0..7), cols c = 2*tx + 32*j (+0/+1), j=0..3.
__device__ __forceinline__ void gemm128(const float* __restrict__ As,
                                        const float* __restrict__ Ws,
                                        int tx, int ty,
                                        unsigned long long acc[8][4]) {
    const float* ap = As + ty * PA;
    const float* bp = Ws + 2 * tx;
#pragma unroll 4
    for (int k = 0; k < 128; ++k) {
        unsigned long long av[8], bv[4];
#pragma unroll
        for (int i = 0; i < 8; ++i) {
            float a = ap[i * 16 * PA + k];
            av[i] = pack2(a, a);
        }
#pragma unroll
        for (int j = 0; j < 4; ++j)
            bv[j] = *reinterpret_cast<const unsigned long long*>(bp + k * 128 + 32 * j);
#pragma unroll
        for (int i = 0; i < 8; ++i)
#pragma unroll
            for (int j = 0; j < 4; ++j) ffma2(acc[i][j], av[i], bv[j]);
    }
}

// cooperative 128x128 fp32 weight load into shared
__device__ __forceinline__ void load_w(const float* __restrict__ src, float* dst, int tid) {
    const float4* s4 = (const float4*)src;
    float4* d4 = (float4*)dst;
#pragma unroll
    for (int v = 0; v < 16; ++v) d4[tid + v * 256] = s4[tid + v * 256];
}

// bias + ReLU, write activation back into A-tile, reset accumulators
__device__ __forceinline__ void relu_store(unsigned long long acc[8][4],
                                           const float* __restrict__ B,
                                           float* As, int tx, int ty) {
    float b0v[4], b1v[4];
#pragma unroll
    for (int j = 0; j < 4; ++j) {
        int c = 2 * tx + 32 * j;
        b0v[j] = B[c];
        b1v[j] = B[c + 1];
    }
#pragma unroll
    for (int i = 0; i < 8; ++i) {
        int r = ty + 16 * i;
#pragma unroll
        for (int j = 0; j < 4; ++j) {
            float lo, hi;
            unpack2(acc[i][j], lo, hi);
            int c = 2 * tx + 32 * j;
            As[r * PA + c]     = fmaxf(lo + b0v[j], 0.f);
            As[r * PA + c + 1] = fmaxf(hi + b1v[j], 0.f);
            acc[i][j] = 0ULL;
        }
    }
}

// ---------------- fused edge MLP + LN + residual + scatter ----------------
__global__ void __launch_bounds__(256, 1)
edge_kernel(const float* __restrict__ W0, const float* __restrict__ B0,
            const float* __restrict__ W1, const float* __restrict__ B1,
            const float* __restrict__ W2, const float* __restrict__ B2,
            const float* __restrict__ G,  const float* __restrict__ Bt,
            const int* __restrict__ eidx) {
    extern __shared__ float smem[];
    float* As = smem;                    // 128 x PA
    float* Ws = smem + 128 * PA;         // 128 x 128
    int* sidx = (int*)(Ws + 128 * 128);  // srow[128], scol[128]

    const int tid = threadIdx.x;
    const int tx = tid & 15, ty = tid >> 4;
    const int base = blockIdx.x * 128;
    const int lr = tid >> 1;
    const int off = (tid & 1) * 64;

    if (tid < 128) {
        sidx[tid]       = eidx[base + tid];        // src node
        sidx[128 + tid] = eidx[NE + base + tid];   // dst node
    }
    __syncthreads();

    unsigned long long acc[8][4];
#pragma unroll
    for (int i = 0; i < 8; ++i)
#pragma unroll
        for (int j = 0; j < 4; ++j) acc[i][j] = 0ULL;

    // layer 0: e_in = [x[row], x[col], e] -> three 128x128 K-blocks
#pragma unroll 1
    for (int s = 0; s < 3; ++s) {
        const float* srcrow;
        if (s == 0)      srcrow = g_x + (size_t)sidx[lr] * D;
        else if (s == 1) srcrow = g_x + (size_t)sidx[128 + lr] * D;
        else             srcrow = g_e + (size_t)(base + lr) * D;
        float* ad = As + lr * PA + off;
#pragma unroll
        for (int v = 0; v < 16; ++v) {
            float4 t = *(const float4*)(srcrow + off + v * 4);
            ad[v * 4 + 0] = t.x; ad[v * 4 + 1] = t.y;
            ad[v * 4 + 2] = t.z; ad[v * 4 + 3] = t.w;
        }
        load_w(W0 + (size_t)s * 128 * 128, Ws, tid);
        __syncthreads();
        gemm128(As, Ws, tx, ty, acc);
        __syncthreads();
    }

    relu_store(acc, B0, As, tx, ty);
    load_w(W1, Ws, tid);
    __syncthreads();
    gemm128(As, Ws, tx, ty, acc);
    __syncthreads();

    relu_store(acc, B1, As, tx, ty);
    load_w(W2, Ws, tid);
    __syncthreads();
    gemm128(As, Ws, tx, ty, acc);

    // epilogue: bias, LayerNorm, residual, store, scatter-add
    float gm0[4], gm1[4], bt0[4], bt1[4], bb0[4], bb1[4];
#pragma unroll
    for (int j = 0; j < 4; ++j) {
        int c = 2 * tx + 32 * j;
        gm0[j] = G[c];  gm1[j] = G[c + 1];
        bt0[j] = Bt[c]; bt1[j] = Bt[c + 1];
        bb0[j] = B2[c]; bb1[j] = B2[c + 1];
    }
#pragma unroll
    for (int i = 0; i < 8; ++i) {
        int r = ty + 16 * i;
        int m = base + r;
        float h0[4], h1[4];
        float s1 = 0.f, s2 = 0.f;
#pragma unroll
        for (int j = 0; j < 4; ++j) {
            float lo, hi;
            unpack2(acc[i][j], lo, hi);
            lo += bb0[j]; hi += bb1[j];
            h0[j] = lo; h1[j] = hi;
            s1 += lo + hi;
            s2 += lo * lo + hi * hi;
        }
#pragma unroll
        for (int o = 8; o; o >>= 1) {
            s1 += __shfl_xor_sync(0xffffffffu, s1, o);
            s2 += __shfl_xor_sync(0xffffffffu, s2, o);
        }
        float mean = s1 * (1.f / D);
        float var  = s2 * (1.f / D) - mean * mean;
        float rstd = rsqrtf(var + EPSLN);
        int dstn = sidx[128 + r];
        float* erow = g_e + (size_t)m * D;
        float* arow = g_agg + (size_t)dstn * D;
#pragma unroll
        for (int j = 0; j < 4; ++j) {
            int c = 2 * tx + 32 * j;
            float y0 = gm0[j] * (h0[j] - mean) * rstd + bt0[j] + erow[c];
            float y1 = gm1[j] * (h1[j] - mean) * rstd + bt1[j] + erow[c + 1];
            *(float2*)(erow + c) = make_float2(y0, y1);
            atomicAdd(arow + c,     y0);
            atomicAdd(arow + c + 1, y1);
        }
    }
}

// ---------------- fused node MLP + LN + residual ----------------
__global__ void __launch_bounds__(256, 1)
node_kernel(const float* __restrict__ W0, const float* __restrict__ B0,
            const float* __restrict__ W1, const float* __restrict__ B1,
            const float* __restrict__ W2, const float* __restrict__ B2,
            const float* __restrict__ G,  const float* __restrict__ Bt) {
    extern __shared__ float smem[];
    float* As = smem;
    float* Ws = smem + 128 * PA;

    const int tid = threadIdx.x;
    const int tx = tid & 15, ty = tid >> 4;
    const int base = blockIdx.x * 128;
    const int lr = tid >> 1;
    const int off = (tid & 1) * 64;

    unsigned long long acc[8][4];
#pragma unroll
    for (int i = 0; i < 8; ++i)
#pragma unroll
        for (int j = 0; j < 4; ++j) acc[i][j] = 0ULL;

    // layer 0: n_in = [x, agg]
#pragma unroll 1
    for (int s = 0; s < 2; ++s) {
        int m = base + lr;
        float* ad = As + lr * PA + off;
        if (m < NN) {
            const float* srcrow = (s == 0 ? g_x : g_agg) + (size_t)m * D;
#pragma unroll
            for (int v = 0; v < 16; ++v) {
                float4 t = *(const float4*)(srcrow + off + v * 4);
                ad[v * 4 + 0] = t.x; ad[v * 4 + 1] = t.y;
                ad[v * 4 + 2] = t.z; ad[v * 4 + 3] = t.w;
            }
        } else {
#pragma unroll
            for (int v = 0; v < 64; ++v) ad[v] = 0.f;
        }
        load_w(W0 + (size_t)s * 128 * 128, Ws, tid);
        __syncthreads();
        gemm128(As, Ws, tx, ty, acc);
        __syncthreads();
    }

    relu_store(acc, B0, As, tx, ty);
    load_w(W1, Ws, tid);
    __syncthreads();
    gemm128(As, Ws, tx, ty, acc);
    __syncthreads();

    relu_store(acc, B1, As, tx, ty);
    load_w(W2, Ws, tid);
    __syncthreads();
    gemm128(As, Ws, tx, ty, acc);

    float gm0[4], gm1[4], bt0[4], bt1[4], bb0[4], bb1[4];
#pragma unroll
    for (int j = 0; j < 4; ++j) {
        int c = 2 * tx + 32 * j;
        gm0[j] = G[c];  gm1[j] = G[c + 1];
        bt0[j] = Bt[c]; bt1[j] = Bt[c + 1];
        bb0[j] = B2[c]; bb1[j] = B2[c + 1];
    }
#pragma unroll
    for (int i = 0; i < 8; ++i) {
        int r = ty + 16 * i;
        int m = base + r;
        float h0[4], h1[4];
        float s1 = 0.f, s2 = 0.f;
#pragma unroll
        for (int j = 0; j < 4; ++j) {
            float lo, hi;
            unpack2(acc[i][j], lo, hi);
            lo += bb0[j]; hi += bb1[j];
            h0[j] = lo; h1[j] = hi;
            s1 += lo + hi;
            s2 += lo * lo + hi * hi;
        }
#pragma unroll
        for (int o = 8; o; o >>= 1) {
            s1 += __shfl_xor_sync(0xffffffffu, s1, o);
            s2 += __shfl_xor_sync(0xffffffffu, s2, o);
        }
        float mean = s1 * (1.f / D);
        float var  = s2 * (1.f / D) - mean * mean;
        float rstd = rsqrtf(var + EPSLN);
        if (m < NN) {
            float* xrow = g_x + (size_t)m * D;
#pragma unroll
            for (int j = 0; j < 4; ++j) {
                int c = 2 * tx + 32 * j;
                float y0 = gm0[j] * (h0[j] - mean) * rstd + bt0[j] + xrow[c];
                float y1 = gm1[j] * (h1[j] - mean) * rstd + bt1[j] + xrow[c + 1];
                *(float2*)(xrow + c) = make_float2(y0, y1);
            }
        }
    }
}

// ---------------- host launch (graph-capturable) ----------------
extern "C" void kernel_launch(void* const* d_in, const int* in_sizes, int n_in,
                              void* d_out, int out_size) {
    const float* x    = (const float*)d_in[0];
    const float* ea   = (const float*)d_in[1];
    const float* eW0  = (const float*)d_in[2];
    const float* eB0  = (const float*)d_in[3];
    const float* eW1  = (const float*)d_in[4];
    const float* eB1  = (const float*)d_in[5];
    const float* eW2  = (const float*)d_in[6];
    const float* eB2  = (const float*)d_in[7];
    const float* eG   = (const float*)d_in[8];
    const float* eBt  = (const float*)d_in[9];
    const float* nW0  = (const float*)d_in[10];
    const float* nB0  = (const float*)d_in[11];
    const float* nW1  = (const float*)d_in[12];
    const float* nB1  = (const float*)d_in[13];
    const float* nW2  = (const float*)d_in[14];
    const float* nB2  = (const float*)d_in[15];
    const float* nG   = (const float*)d_in[16];
    const float* nBt  = (const float*)d_in[17];
    const int*   eidx = (const int*)d_in[18];

    float *px, *pe, *pagg;
    cudaGetSymbolAddress((void**)&px, g_x);
    cudaGetSymbolAddress((void**)&pe, g_e);
    cudaGetSymbolAddress((void**)&pagg, g_agg);

    cudaFuncSetAttribute(edge_kernel, cudaFuncAttributeMaxDynamicSharedMemorySize, SMEM_BYTES);
    cudaFuncSetAttribute(node_kernel, cudaFuncAttributeMaxDynamicSharedMemorySize, SMEM_BYTES);

    cudaMemcpyAsync(px, x,  (size_t)NN * D * sizeof(float), cudaMemcpyDeviceToDevice);
    cudaMemcpyAsync(pe, ea, (size_t)NE * D * sizeof(float), cudaMemcpyDeviceToDevice);

    for (int it = 0; it < ITERS; ++it) {
        cudaMemsetAsync(pagg, 0, (size_t)NN * D * sizeof(float));
        edge_kernel<<<NE / 128, 256, SMEM_BYTES>>>(
            eW0 + (size_t)it * 3 * D * D, eB0 + it * D,
            eW1 + (size_t)it * D * D,     eB1 + it * D,
            eW2 + (size_t)it * D * D,     eB2 + it * D,
            eG + it * D, eBt + it * D, eidx);
        node_kernel<<<(NN + 127) / 128, 256, SMEM_BYTES>>>(
            nW0 + (size_t)it * 2 * D * D, nB0 + it * D,
            nW1 + (size_t)it * D * D,     nB1 + it * D,
            nW2 + (size_t)it * D * D,     nB2 + it * D,
            nG + it * D, nBt + it * D);
    }

    cudaMemcpyAsync(d_out, px, (size_t)NN * D * sizeof(float), cudaMemcpyDeviceToDevice);
    cudaMemcpyAsync((float*)d_out + (size_t)NN * D, pe,
                    (size_t)NE * D * sizeof(float), cudaMemcpyDeviceToDevice);
}